// round 1
// baseline (speedup 1.0000x reference)
#include <cuda_runtime.h>

#define B        1024
#define NUM_VARS 2048
#define LEAVES   (2 * NUM_VARS)            // 4096
#define LEVELS   12
#define WIDTH    4096
#define FANIN    4
#define TOTAL    (LEAVES + LEVELS * WIDTH) // 53248

// Node-major value buffer: g_buf[node][batch]. ~218 MB static device array
// (allocation-free scratch per harness rules). Only ~needed rows are touched.
__device__ float g_buf[(size_t)TOTAL * B];
__device__ int   g_needed[TOTAL];
__device__ int   g_list[LEVELS][WIDTH];
__device__ int   g_count[LEVELS];

// ---------------------------------------------------------------------------
// Pass 1: backward reachability from the root. Single block; levels processed
// top-down (children of level l are strictly < LEAVES + l*WIDTH, so each
// level's list is complete before we read it). atomicExch dedupes appends.
// ---------------------------------------------------------------------------
__global__ void __launch_bounds__(1024, 1)
backward_mark(const int* __restrict__ child_idx) {
    const int tid = threadIdx.x;
    for (int i = tid; i < TOTAL; i += 1024) g_needed[i] = 0;
    if (tid < LEVELS) g_count[tid] = 0;
    __syncthreads();
    if (tid == 0) {
        g_needed[TOTAL - 1] = 1;
        g_list[LEVELS - 1][0] = TOTAL - 1;
        g_count[LEVELS - 1] = 1;
    }
    __syncthreads();

    for (int l = LEVELS - 1; l >= 0; --l) {
        const int cnt = g_count[l];
        for (int i = tid; i < cnt; i += 1024) {
            const int g = g_list[l][i];
            const int w = g - LEAVES - l * WIDTH;
            const int4 ch = ((const int4*)child_idx)[l * WIDTH + w];
            const int cs[4] = {ch.x, ch.y, ch.z, ch.w};
            #pragma unroll
            for (int f = 0; f < FANIN; ++f) {
                const int c = cs[f];
                if (atomicExch(&g_needed[c], 1) == 0 && c >= LEAVES) {
                    const int ll = (c - LEAVES) / WIDTH;   // strictly < l
                    const int pos = atomicAdd(&g_count[ll], 1);
                    g_list[ll][pos] = c;
                }
            }
        }
        __syncthreads();  // level l's appends visible before reading level l-1
    }
}

// ---------------------------------------------------------------------------
// Pass 2: scatter needed leaves into node-major layout.
// Coalesced read of x (consecutive threads -> consecutive v, same b);
// scattered 4B stores only for the ~7% of leaf rows that are reachable.
// ---------------------------------------------------------------------------
__global__ void scatter_leaves(const float* __restrict__ x) {
    const int idx = blockIdx.x * blockDim.x + threadIdx.x;  // over B*NUM_VARS
    if (idx >= B * NUM_VARS) return;
    const int b = idx >> 11;      // idx / NUM_VARS
    const int v = idx & 2047;     // idx % NUM_VARS
    const float val = x[idx];
    if (g_needed[v])            g_buf[(size_t)v * B + b] = val;
    if (g_needed[v + NUM_VARS]) g_buf[(size_t)(v + NUM_VARS) * B + b] = 1.0f - val;
}

// ---------------------------------------------------------------------------
// Pass 3: forward evaluation of one level's needed nodes.
// One block (1024 threads = full batch) per node; grid-stride over the
// device-side count. All gathers are coalesced (warp spans batch dim).
// ---------------------------------------------------------------------------
__global__ void __launch_bounds__(1024, 1)
level_eval(const int* __restrict__ child_idx,
           const int* __restrict__ op_type,
           int l, float* __restrict__ out) {
    const int cnt = g_count[l];
    const int b = threadIdx.x;
    for (int i = blockIdx.x; i < cnt; i += gridDim.x) {
        const int g = g_list[l][i];
        const int w = g - LEAVES - l * WIDTH;
        const int4 ch = ((const int4*)child_idx)[l * WIDTH + w];
        const float v0 = g_buf[(size_t)ch.x * B + b];
        const float v1 = g_buf[(size_t)ch.y * B + b];
        const float v2 = g_buf[(size_t)ch.z * B + b];
        const float v3 = g_buf[(size_t)ch.w * B + b];
        const float r = (op_type[l * WIDTH + w] == 0)
                            ? (v0 * v1) * (v2 * v3)
                            : (v0 + v1) + (v2 + v3);
        g_buf[(size_t)g * B + b] = r;
        if (g == TOTAL - 1) out[b] = r;   // root -> kernel output
    }
}

// ---------------------------------------------------------------------------
// Launch: inputs per metadata order: x (f32), child_idx (i32), op_type (i32).
// Stream-ordered; graph-capturable (launches only, no sync, no alloc).
// ---------------------------------------------------------------------------
extern "C" void kernel_launch(void* const* d_in, const int* in_sizes, int n_in,
                              void* d_out, int out_size) {
    const float* x         = (const float*)d_in[0];
    const int*   child_idx = (const int*)  d_in[1];
    const int*   op_type   = (const int*)  d_in[2];
    float*       out       = (float*)d_out;

    backward_mark<<<1, 1024>>>(child_idx);

    const int n = B * NUM_VARS;
    scatter_leaves<<<(n + 255) / 256, 256>>>(x);

    for (int l = 0; l < LEVELS; ++l) {
        level_eval<<<128, 1024>>>(child_idx, op_type, l, out);
    }
}

// round 3
// speedup vs baseline: 1.0679x; 1.0679x over previous
#include <cuda_runtime.h>

#define B        1024
#define NUM_VARS 2048
#define LEAVES   (2 * NUM_VARS)            // 4096
#define LEVELS   12
#define WIDTH    4096
#define FANIN    4
#define TOTAL    (LEAVES + LEVELS * WIDTH) // 53248

// ---------------------------------------------------------------------------
// Static device scratch (allocation-free per harness rules).
// Sized for the absolute worst case (all nodes needed) so correctness never
// depends on the sparsity estimate; perf does.
// ---------------------------------------------------------------------------
__device__ float g_val[(size_t)TOTAL * B];       // compact node values [cid][b]
__device__ int   g_needed[TOTAL];
__device__ int   g_list[LEVELS][WIDTH];          // per-level original ids
__device__ int   g_cnt[LEVELS];
__device__ int   g_off[LEVELS + 1];              // prefix offsets into internal order
__device__ int   g_nleaf;
__device__ int   g_leaflist[LEAVES];             // compact leaf slot -> original leaf id
__device__ int   g_compact[TOTAL];               // original id -> compact id
__device__ int4  g_cch[LEVELS * WIDTH];          // compact children per internal position
__device__ int   g_cop[LEVELS * WIDTH];          // op per internal position

// ---------------------------------------------------------------------------
// Pass 1: backward reachability from the root + build the compacted plan.
// Single block. Levels walked top-down (children of level l live strictly
// below l, so each level's list is complete before it is consumed).
// ---------------------------------------------------------------------------
__global__ void __launch_bounds__(1024, 1)
build_plan(const int* __restrict__ child_idx, const int* __restrict__ op_type) {
    const int tid = threadIdx.x;

    for (int i = tid; i < TOTAL; i += 1024) g_needed[i] = 0;
    if (tid < LEVELS) g_cnt[tid] = 0;
    if (tid == 0) g_nleaf = 0;
    __syncthreads();

    if (tid == 0) {
        g_needed[TOTAL - 1] = 1;
        g_list[LEVELS - 1][0] = TOTAL - 1;
        g_cnt[LEVELS - 1] = 1;
    }
    __syncthreads();

    for (int l = LEVELS - 1; l >= 0; --l) {
        const int cnt = g_cnt[l];
        for (int i = tid; i < cnt; i += 1024) {
            const int g = g_list[l][i];
            const int w = g - LEAVES - l * WIDTH;
            const int4 ch = ((const int4*)child_idx)[l * WIDTH + w];
            const int cs[4] = {ch.x, ch.y, ch.z, ch.w};
            #pragma unroll
            for (int f = 0; f < FANIN; ++f) {
                const int c = cs[f];
                if (atomicExch(&g_needed[c], 1) == 0) {
                    if (c >= LEAVES) {
                        const int ll = (c - LEAVES) >> 12;           // / WIDTH
                        const int pos = atomicAdd(&g_cnt[ll], 1);
                        g_list[ll][pos] = c;
                    } else {
                        const int pos = atomicAdd(&g_nleaf, 1);
                        g_leaflist[pos] = c;
                    }
                }
            }
        }
        __syncthreads();
    }

    // Level offsets within the flattened internal ordering.
    if (tid == 0) {
        int o = 0;
        for (int l = 0; l < LEVELS; ++l) { g_off[l] = o; o += g_cnt[l]; }
        g_off[LEVELS] = o;
    }
    __syncthreads();

    // Compact id assignment: leaves first, then internal nodes level-by-level.
    const int NL = g_nleaf;
    for (int j = tid; j < NL; j += 1024) g_compact[g_leaflist[j]] = j;
    for (int l = 0; l < LEVELS; ++l) {
        const int cnt = g_cnt[l], base = NL + g_off[l];
        for (int i = tid; i < cnt; i += 1024) g_compact[g_list[l][i]] = base + i;
    }
    __syncthreads();

    // Emit compacted children + ops, flattened by internal position.
    for (int l = 0; l < LEVELS; ++l) {
        const int cnt = g_cnt[l], base = g_off[l];
        for (int i = tid; i < cnt; i += 1024) {
            const int g = g_list[l][i];
            const int w = g - LEAVES - l * WIDTH;
            const int4 ch = ((const int4*)child_idx)[l * WIDTH + w];
            int4 cc;
            cc.x = g_compact[ch.x];
            cc.y = g_compact[ch.y];
            cc.z = g_compact[ch.z];
            cc.w = g_compact[ch.w];
            g_cch[base + i] = cc;
            g_cop[base + i] = op_type[l * WIDTH + w];
        }
    }
}

// ---------------------------------------------------------------------------
// Pass 2: fused forward evaluation. Each block owns 8 batch columns and walks
// all levels; batch independence means no cross-block sync is ever needed.
// Thread layout: bb = tid&7 (batch within block), lane = tid>>3 (node lane).
// ---------------------------------------------------------------------------
#define BB 8
__global__ void __launch_bounds__(512, 1)
forward_eval(const float* __restrict__ x, float* __restrict__ out) {
    const int bb   = threadIdx.x & (BB - 1);
    const int lane = threadIdx.x >> 3;           // 0..63
    const int bg   = blockIdx.x * BB + bb;

    const int NL = g_nleaf;
    const int NI = g_off[LEVELS];

    // Leaves: gather needed variables straight from x.
    for (int j = lane; j < NL; j += 64) {
        const int L = g_leaflist[j];
        float v;
        if (L < NUM_VARS) v = x[bg * NUM_VARS + L];
        else              v = 1.0f - x[bg * NUM_VARS + (L - NUM_VARS)];
        g_val[(size_t)j * B + bg] = v;
    }
    __syncthreads();

    // Internal levels in topological order.
    for (int l = 0; l < LEVELS; ++l) {
        const int s = g_off[l], e = g_off[l + 1];
        for (int i = s + lane; i < e; i += 64) {
            const int4 cc = g_cch[i];
            const float v0 = g_val[(size_t)cc.x * B + bg];
            const float v1 = g_val[(size_t)cc.y * B + bg];
            const float v2 = g_val[(size_t)cc.z * B + bg];
            const float v3 = g_val[(size_t)cc.w * B + bg];
            const float r = (g_cop[i] == 0) ? (v0 * v1) * (v2 * v3)
                                            : (v0 + v1) + (v2 + v3);
            g_val[(size_t)(NL + i) * B + bg] = r;
        }
        __syncthreads();
    }

    // Root is the last internal node in compact order.
    if (lane == 0) out[bg] = g_val[(size_t)(NL + NI - 1) * B + bg];
}

// ---------------------------------------------------------------------------
// Launch: x (f32), child_idx (i32), op_type (i32). Graph-capturable.
// ---------------------------------------------------------------------------
extern "C" void kernel_launch(void* const* d_in, const int* in_sizes, int n_in,
                              void* d_out, int out_size) {
    const float* x         = (const float*)d_in[0];
    const int*   child_idx = (const int*)  d_in[1];
    const int*   op_type   = (const int*)  d_in[2];
    float*       out       = (float*)d_out;

    build_plan<<<1, 1024>>>(child_idx, op_type);
    forward_eval<<<B / BB, 512>>>(x, out);
}

// round 4
// speedup vs baseline: 2.3108x; 2.1639x over previous
#include <cuda_runtime.h>

#define B        1024
#define NUM_VARS 2048
#define LEAVES   (2 * NUM_VARS)            // 4096
#define LEVELS   12
#define WIDTH    4096
#define FANIN    4
#define TOTAL    (LEAVES + LEVELS * WIDTH) // 53248

// ---- smem capacities (fast path; global fallback keeps worst case correct) --
#define LIST_CAP 512     // per-level node list entries kept in smem (build)
#define VCAP     4096    // compact values kept in smem (forward)
#define VPAD     9       // val row stride (bank-conflict padding)
#define PCAP     1024    // plan nodes cached in smem (forward)
#define LCAP     2048    // leaf list entries cached in smem (forward)
#define BBK      8       // batch columns per forward block

// ---------------------------------------------------------------------------
// Global fallback / interchange buffers (allocation-free static scratch).
// ---------------------------------------------------------------------------
__device__ float g_val[(size_t)TOTAL * B];   // overflow value storage [cid][b]
__device__ int   g_list[LEVELS][WIDTH];      // per-level list spill (pos>=LIST_CAP)
__device__ int   g_leaflist[LEAVES];         // compact leaf slot -> original leaf id
__device__ int4  g_cch[LEVELS * WIDTH];      // compact children (op in bit31 of .x)
__device__ int   g_off[LEVELS + 1];          // level offsets in internal order
__device__ int   g_nleaf;

// ---------------------------------------------------------------------------
// Pass 1: backward reachability + compacted plan, all state in SMEM.
//   bits  : dedupe bitset, smem atomicOr      (6656 B)
//   cmap  : original id -> compact id, ushort (106496 B)
//   slist : per-level lists, cap LIST_CAP     (24576 B)
// ---------------------------------------------------------------------------
#define BP_SMEM (6656 + (TOTAL * 2) + (LEVELS * LIST_CAP * 4))

__global__ void __launch_bounds__(1024, 1)
build_plan(const int* __restrict__ child_idx, const int* __restrict__ op_type) {
    extern __shared__ unsigned char sm[];
    unsigned int*   bits = (unsigned int*)sm;                      // 1664 words
    unsigned short* cmap = (unsigned short*)(sm + 6656);           // TOTAL
    int*            slist = (int*)(sm + 6656 + TOTAL * 2);         // [LEVELS][LIST_CAP]
    __shared__ int scnt[LEVELS];
    __shared__ int soff[LEVELS + 1];
    __shared__ int snleaf;

    const int tid = threadIdx.x;

    for (int i = tid; i < (TOTAL + 31) / 32; i += 1024) bits[i] = 0u;
    if (tid < LEVELS) scnt[tid] = 0;
    if (tid == 0) snleaf = 0;
    __syncthreads();

    if (tid == 0) {
        scnt[LEVELS - 1] = 1;
        slist[(LEVELS - 1) * LIST_CAP] = TOTAL - 1;
        bits[(TOTAL - 1) >> 5] |= 1u << ((TOTAL - 1) & 31);
    }
    __syncthreads();

    // Top-down walk: children of level l are strictly below l.
    for (int l = LEVELS - 1; l >= 0; --l) {
        const int cnt = scnt[l];
        for (int i = tid; i < cnt; i += 1024) {
            const int g = (i < LIST_CAP) ? slist[l * LIST_CAP + i] : g_list[l][i];
            const int w = g - LEAVES - l * WIDTH;
            const int4 ch = ((const int4*)child_idx)[l * WIDTH + w];
            const int cs[4] = {ch.x, ch.y, ch.z, ch.w};
            #pragma unroll
            for (int f = 0; f < FANIN; ++f) {
                const int c = cs[f];
                const unsigned int m = 1u << (c & 31);
                const unsigned int old = atomicOr(&bits[c >> 5], m);
                if (!(old & m)) {                       // first discoverer
                    if (c >= LEAVES) {
                        const int ll = (c - LEAVES) >> 12;         // / WIDTH
                        const int pos = atomicAdd(&scnt[ll], 1);
                        if (pos < LIST_CAP) slist[ll * LIST_CAP + pos] = c;
                        else                g_list[ll][pos] = c;
                    } else {
                        const int pos = atomicAdd(&snleaf, 1);
                        g_leaflist[pos] = c;
                    }
                }
            }
        }
        __syncthreads();
    }

    // Level offsets (internal ordering).
    if (tid == 0) {
        int o = 0;
        for (int l = 0; l < LEVELS; ++l) { soff[l] = o; o += scnt[l]; }
        soff[LEVELS] = o;
        g_nleaf = snleaf;
    }
    if (tid < LEVELS + 1) { /* placeholder to keep divergence simple */ }
    __syncthreads();
    if (tid <= LEVELS) g_off[tid] = soff[tid];

    // Compact id assignment into smem map: leaves first, then internal.
    const int NL = snleaf;
    for (int j = tid; j < NL; j += 1024)
        cmap[g_leaflist[j]] = (unsigned short)j;
    for (int l = 0; l < LEVELS; ++l) {
        const int cnt = scnt[l], base = NL + soff[l];
        for (int i = tid; i < cnt; i += 1024) {
            const int g = (i < LIST_CAP) ? slist[l * LIST_CAP + i] : g_list[l][i];
            cmap[g] = (unsigned short)(base + i);
        }
    }
    __syncthreads();

    // Emit compacted plan; op packed into bit31 of child0.
    for (int l = 0; l < LEVELS; ++l) {
        const int cnt = scnt[l], base = soff[l];
        for (int i = tid; i < cnt; i += 1024) {
            const int g = (i < LIST_CAP) ? slist[l * LIST_CAP + i] : g_list[l][i];
            const int w = g - LEAVES - l * WIDTH;
            const int4 ch = ((const int4*)child_idx)[l * WIDTH + w];
            const int op = op_type[l * WIDTH + w];
            int4 cc;
            cc.x = (int)cmap[ch.x] | (op << 31);
            cc.y = (int)cmap[ch.y];
            cc.z = (int)cmap[ch.z];
            cc.w = (int)cmap[ch.w];
            g_cch[base + i] = cc;
        }
    }
}

// ---------------------------------------------------------------------------
// Pass 2: fused forward evaluation, values + plan in SMEM.
// Each block owns BBK batch columns; bb = tid&7, lane = tid>>3 (64 lanes).
// ---------------------------------------------------------------------------
#define FW_SMEM ((VCAP * VPAD * 4) + (PCAP * 16) + (LCAP * 4))

__global__ void __launch_bounds__(512, 1)
forward_eval(const float* __restrict__ x, float* __restrict__ out) {
    extern __shared__ unsigned char sm[];
    float* val  = (float*)sm;                                   // [VCAP][VPAD]
    int4*  pcch = (int4*)(sm + VCAP * VPAD * 4);                // [PCAP]
    int*   plf  = (int*)(sm + VCAP * VPAD * 4 + PCAP * 16);     // [LCAP]
    __shared__ int s_off[LEVELS + 1];
    __shared__ int s_nl;

    const int tid = threadIdx.x;
    if (tid <= LEVELS) s_off[tid] = g_off[tid];
    if (tid == LEVELS + 1) s_nl = g_nleaf;
    __syncthreads();
    const int NL = s_nl;
    const int NI = s_off[LEVELS];

    // Cache plan + leaf list in smem.
    {
        const int ni = (NI < PCAP) ? NI : PCAP;
        for (int i = tid; i < ni; i += 512) pcch[i] = g_cch[i];
        const int nl = (NL < LCAP) ? NL : LCAP;
        for (int j = tid; j < nl; j += 512) plf[j] = g_leaflist[j];
    }
    __syncthreads();

    const int bb   = tid & (BBK - 1);
    const int lane = tid >> 3;                // 0..63
    const int bg   = blockIdx.x * BBK + bb;

    // Leaves from x (L2-hot across replays).
    for (int j = lane; j < NL; j += 64) {
        const int L = (j < LCAP) ? plf[j] : g_leaflist[j];
        const float xv = x[bg * NUM_VARS + (L & (NUM_VARS - 1))];
        const float v  = (L < NUM_VARS) ? xv : 1.0f - xv;
        if (j < VCAP) val[j * VPAD + bb] = v;
        else          g_val[(size_t)j * B + bg] = v;
    }
    __syncthreads();

    // Topological levels: all-SMEM in the fast path.
    for (int l = 0; l < LEVELS; ++l) {
        const int s = s_off[l], e = s_off[l + 1];
        for (int i = s + lane; i < e; i += 64) {
            const int4 cc = (i < PCAP) ? pcch[i] : g_cch[i];
            const int op = (unsigned int)cc.x >> 31;
            const int c0 = cc.x & 0x7FFFFFFF;
            #define FETCH(c) ((c) < VCAP ? val[(c) * VPAD + bb] \
                                         : g_val[(size_t)(c) * B + bg])
            const float v0 = FETCH(c0);
            const float v1 = FETCH(cc.y);
            const float v2 = FETCH(cc.z);
            const float v3 = FETCH(cc.w);
            #undef FETCH
            const float r = op ? (v0 + v1) + (v2 + v3)
                               : (v0 * v1) * (v2 * v3);
            const int cid = NL + i;
            if (cid < VCAP) val[cid * VPAD + bb] = r;
            else            g_val[(size_t)cid * B + bg] = r;
        }
        __syncthreads();
    }

    // Root = last internal node in compact order.
    if (lane == 0) {
        const int rc = NL + NI - 1;
        out[bg] = (rc < VCAP) ? val[rc * VPAD + bb]
                              : g_val[(size_t)rc * B + bg];
    }
}

// ---------------------------------------------------------------------------
// Launch: x (f32), child_idx (i32), op_type (i32). Graph-capturable:
// attribute sets are host-side (not stream ops); launches only on the stream.
// ---------------------------------------------------------------------------
extern "C" void kernel_launch(void* const* d_in, const int* in_sizes, int n_in,
                              void* d_out, int out_size) {
    const float* x         = (const float*)d_in[0];
    const int*   child_idx = (const int*)  d_in[1];
    const int*   op_type   = (const int*)  d_in[2];
    float*       out       = (float*)d_out;

    cudaFuncSetAttribute(build_plan,
                         cudaFuncAttributeMaxDynamicSharedMemorySize, BP_SMEM);
    cudaFuncSetAttribute(forward_eval,
                         cudaFuncAttributeMaxDynamicSharedMemorySize, FW_SMEM);

    build_plan<<<1, 1024, BP_SMEM>>>(child_idx, op_type);
    forward_eval<<<B / BBK, 512, FW_SMEM>>>(x, out);
}

// round 5
// speedup vs baseline: 2.5515x; 1.1042x over previous
#include <cuda_runtime.h>

#define B        1024
#define NUM_VARS 2048
#define LEAVES   (2 * NUM_VARS)            // 4096
#define LEVELS   12
#define WIDTH    4096
#define TOTAL    (LEAVES + LEVELS * WIDTH) // 53248

#define BBK      8                 // batch columns per block
#define NTHR     512
#define NLANE    (NTHR / BBK)      // 64 node lanes
#define NBLK     (B / BBK)         // 128 blocks

// smem fast-path capacities (global spill keeps the worst case correct)
#define LIST_CAP 256               // plan entries per level in smem
#define LEAF_CAP 1024              // leaf entries in smem
#define VCAP     1536              // compact values in smem
#define VPAD     9                 // bank-conflict padding

// ---------------------------------------------------------------------------
// Global spill / fallback scratch (allocation-free static arrays).
// Each block uses only its own slice; normally untouched.
// ---------------------------------------------------------------------------
__device__ float g_val[(size_t)TOTAL * B];                 // [cid][b] overflow values
__device__ int4  g_plan_spill[NBLK][LEVELS][WIDTH];        // per-block plan overflow
__device__ int2  g_leaf_spill[NBLK][LEAVES];               // per-block leaf overflow

// smem layout (byte offsets; all 16B-aligned where needed)
#define SM_BITS   0
#define SM_CMAP   6656                                   // bits: 1664 words
#define SM_PLAN   (SM_CMAP + TOTAL * 2)                  // 113152 (16B aligned)
#define SM_LEAF   (SM_PLAN + LEVELS * LIST_CAP * 16)     // 162304
#define SM_VAL    (SM_LEAF + LEAF_CAP * 8)               // 170496
#define SM_TOTAL  (SM_VAL + VCAP * VPAD * 4)             // 225792 B (< 227KB)

// ---------------------------------------------------------------------------
// Single fused kernel. Every block independently:
//   1) rebuilds the backward-reachable plan in its own SMEM (identical work,
//      parallel across SMs, child_idx L2-broadcast-hot),
//   2) evaluates its BBK batch columns forward, all-SMEM.
// No cross-block communication; one launch total.
// ---------------------------------------------------------------------------
__global__ void __launch_bounds__(NTHR, 1)
eval_all(const float* __restrict__ x,
         const int*   __restrict__ child_idx,
         const int*   __restrict__ op_type,
         float*       __restrict__ out)
{
    extern __shared__ unsigned char sm[];
    unsigned int*   bits = (unsigned int*)  (sm + SM_BITS);
    unsigned short* cmap = (unsigned short*)(sm + SM_CMAP);
    int4*           plan = (int4*)          (sm + SM_PLAN);  // [LEVELS][LIST_CAP]
    int2*           leaf = (int2*)          (sm + SM_LEAF);  // [LEAF_CAP]
    float*          val  = (float*)         (sm + SM_VAL);   // [VCAP][VPAD]

    __shared__ int scnt[LEVELS];
    __shared__ int snleaf, snnodes;

    const int tid = threadIdx.x;
    const int blk = blockIdx.x;

    // ---- init ----
    for (int i = tid; i < (TOTAL + 31) / 32; i += NTHR) bits[i] = 0u;
    if (tid < LEVELS) scnt[tid] = 0;
    if (tid == 0) { snleaf = 0; snnodes = 1; }
    __syncthreads();
    if (tid == 0) {
        // seed: root node, compact id 0
        plan[(LEVELS - 1) * LIST_CAP].x = TOTAL - 1;
        plan[(LEVELS - 1) * LIST_CAP].w = 0;
        scnt[LEVELS - 1] = 1;
        bits[(TOTAL - 1) >> 5] |= 1u << ((TOTAL - 1) & 31);
        cmap[TOTAL - 1] = 0;
    }
    __syncthreads();

    // ---- backward discovery, top-down; emits fully-resolved plan entries ----
    for (int l = LEVELS - 1; l >= 0; --l) {
        const int cnt = scnt[l];                 // complete: set by levels > l
        for (int ibase = 0; ibase < cnt; ibase += NTHR) {
            const int i = ibase + tid;
            int4 entry; int4 ch; int myop = 0;
            // phase A: claim children, assign cids, schedule them
            if (i < cnt) {
                entry = (i < LIST_CAP) ? plan[l * LIST_CAP + i]
                                       : g_plan_spill[blk][l][i];
                const int g = entry.x;
                const int w = g - LEAVES - l * WIDTH;
                ch   = ((const int4*)child_idx)[l * WIDTH + w];
                myop = op_type[l * WIDTH + w];
                const int cs[4] = {ch.x, ch.y, ch.z, ch.w};
                #pragma unroll
                for (int f = 0; f < 4; ++f) {
                    const int c = cs[f];
                    const unsigned int m = 1u << (c & 31);
                    const unsigned int old = atomicOr(&bits[c >> 5], m);
                    if (!(old & m)) {                      // first discoverer
                        const int cid = atomicAdd(&snnodes, 1);
                        cmap[c] = (unsigned short)cid;
                        if (c >= LEAVES) {
                            const int ll  = (c - LEAVES) >> 12;     // / WIDTH
                            const int pos = atomicAdd(&scnt[ll], 1);
                            if (pos < LIST_CAP) {
                                plan[ll * LIST_CAP + pos].x = c;
                                plan[ll * LIST_CAP + pos].w = cid;
                            } else {
                                g_plan_spill[blk][ll][pos].x = c;
                                g_plan_spill[blk][ll][pos].w = cid;
                            }
                        } else {
                            const int pos = atomicAdd(&snleaf, 1);
                            if (pos < LEAF_CAP) leaf[pos] = make_int2(c, cid);
                            else                g_leaf_spill[blk][pos] = make_int2(c, cid);
                        }
                    }
                }
            }
            __syncthreads();   // all cmap writes for this level's children visible
            // phase B: resolve child cids into the plan entry
            if (i < cnt) {
                int4 e2;
                e2.x = entry.x;
                e2.y = (int)cmap[ch.x] | ((int)cmap[ch.y] << 16);
                e2.z = (int)cmap[ch.z] | ((int)cmap[ch.w] << 16);
                e2.w = (entry.w & 0xFFFF) | (myop << 31);
                if (i < LIST_CAP) plan[l * LIST_CAP + i] = e2;
                else              g_plan_spill[blk][l][i] = e2;
            }
            __syncthreads();
        }
    }
    __syncthreads();

    // ---- forward evaluation: this block's BBK batch columns ----
    const int bb   = tid & (BBK - 1);
    const int lane = tid >> 3;                  // 0..63
    const int bg   = blk * BBK + bb;
    const int NL   = snleaf;

    // leaves straight from x (L2-hot across replays)
    for (int j = lane; j < NL; j += NLANE) {
        const int2 e = (j < LEAF_CAP) ? leaf[j] : g_leaf_spill[blk][j];
        const float xv = x[bg * NUM_VARS + (e.x & (NUM_VARS - 1))];
        const float v  = (e.x < NUM_VARS) ? xv : 1.0f - xv;
        if (e.y < VCAP) val[e.y * VPAD + bb] = v;
        else            g_val[(size_t)e.y * B + bg] = v;
    }
    __syncthreads();

    // topological levels: pure SMEM in the fast path
    for (int l = 0; l < LEVELS; ++l) {
        const int cnt = scnt[l];
        for (int i = lane; i < cnt; i += NLANE) {
            const int4 e = (i < LIST_CAP) ? plan[l * LIST_CAP + i]
                                          : g_plan_spill[blk][l][i];
            const int c0 = e.y & 0xFFFF, c1 = ((unsigned)e.y) >> 16;
            const int c2 = e.z & 0xFFFF, c3 = ((unsigned)e.z) >> 16;
            const int dest = e.w & 0xFFFF;
            const int op   = ((unsigned)e.w) >> 31;
            #define FETCH(c) ((c) < VCAP ? val[(c) * VPAD + bb] \
                                         : g_val[(size_t)(c) * B + bg])
            const float v0 = FETCH(c0);
            const float v1 = FETCH(c1);
            const float v2 = FETCH(c2);
            const float v3 = FETCH(c3);
            #undef FETCH
            const float r = op ? (v0 + v1) + (v2 + v3)
                               : (v0 * v1) * (v2 * v3);
            if (dest < VCAP) val[dest * VPAD + bb] = r;
            else             g_val[(size_t)dest * B + bg] = r;
        }
        __syncthreads();
    }

    // root has compact id 0
    if (lane == 0) out[bg] = val[bb];
}

// ---------------------------------------------------------------------------
// Launch: x (f32), child_idx (i32), op_type (i32). One kernel; capturable.
// ---------------------------------------------------------------------------
extern "C" void kernel_launch(void* const* d_in, const int* in_sizes, int n_in,
                              void* d_out, int out_size) {
    const float* x         = (const float*)d_in[0];
    const int*   child_idx = (const int*)  d_in[1];
    const int*   op_type   = (const int*)  d_in[2];
    float*       out       = (float*)d_out;

    cudaFuncSetAttribute(eval_all,
                         cudaFuncAttributeMaxDynamicSharedMemorySize, SM_TOTAL);
    eval_all<<<NBLK, NTHR, SM_TOTAL>>>(x, child_idx, op_type, out);
}